// round 1
// baseline (speedup 1.0000x reference)
#include <cuda_runtime.h>

#define MODES 64
#define AUD   16
#define T     32768
#define F     4096
#define NC    513          // coarse entries per mode (t+1 up to 32768 -> c up to 512)

// ---------------- device scratch (no allocations allowed) ----------------
__device__ float  g_d[MODES];              // per-sample damping  d = damp_raw/SR
__device__ float  g_w[MODES];              // per-sample angular freq w = sqrt(lbd - damp^2)/SR
__device__ float  g_amp[AUD * MODES];
__device__ float  g_Ec[MODES * NC], g_Sc[MODES * NC], g_Cc[MODES * NC];   // coarse (n = 64c)
__device__ float  g_Ef[MODES * 64], g_Sf[MODES * 64], g_Cf[MODES * 64];   // fine   (n = r)
__device__ float  g_Ps[MODES * T];         // e^{-d(t+1)} sin(w(t+1))
__device__ float  g_Pc[MODES * T];         // e^{-d(t+1)} cos(w(t+1))
__device__ float  g_spad[AUD * 8192];      // [4095 zeros | signal[0..4096]] per audio
__device__ float2 g_cAB[MODES * AUD];      // (amp*A, amp*B) laid out [m][a]

// ---------------- K1: per-mode params + amps (tiny) ----------------
__global__ void k_setup(const float* __restrict__ freq_linear,
                        const float* __restrict__ amp_value,
                        const float* __restrict__ alpha_params,
                        const float* __restrict__ beta_params)
{
    int m = threadIdx.x;
    if (m >= MODES) return;

    // alpha bins: exp(linspace(ln(0.6), ln(60), 64))
    const float la0 = logf(0.6f), la1 = logf(60.0f);
    const float lb0 = logf(2e-8f), lb1 = logf(2e-6f);

    float asum = 0.f, awsum = 0.f, bsum = 0.f, bwsum = 0.f;
    #pragma unroll 4
    for (int b = 0; b < 64; b++) {
        float frac = (float)b / 63.0f;
        float va = expf(la0 + (la1 - la0) * frac);
        float vb = expf(lb0 + (lb1 - lb0) * frac);
        float spa = log1pf(expf(alpha_params[m * 64 + b]));
        float spb = log1pf(expf(beta_params [m * 64 + b]));
        awsum += spa; asum += spa * va;
        bwsum += spb; bsum += spb * vb;
    }
    float alpha = asum / awsum;
    float beta  = bsum / bwsum;

    float f2pi = freq_linear[m] * 6.28318530717958647692f;
    float lbd  = f2pi * f2pi;
    float dr   = 0.5f * (alpha + beta * lbd);          // per-second damping
    g_d[m] = dr / 16000.0f;
    g_w[m] = sqrtf(lbd - dr * dr) / 16000.0f;

    // amp = 2*sigmoid(x)^ln(10) + 1e-7
    for (int a = 0; a < AUD; a++) {
        float x = amp_value[a * MODES + m];
        float s = 1.0f / (1.0f + expf(-x));
        g_amp[a * MODES + m] = 2.0f * expf(2.30258509299404568f * logf(s)) + 1e-7f;
    }
}

// ---------------- K2: coarse + fine trig/exp tables ----------------
__global__ void k_tables_cf()
{
    int idx = blockIdx.x * blockDim.x + threadIdx.x;
    const int NCOARSE = MODES * NC;
    if (idx < NCOARSE) {
        int m = idx / NC, c = idx % NC;
        float n = (float)(c << 6);
        float s, co;
        sincosf(g_w[m] * n, &s, &co);
        g_Ec[idx] = expf(-g_d[m] * n);
        g_Sc[idx] = s;
        g_Cc[idx] = co;
    } else if (idx < NCOARSE + MODES * 64) {
        int j = idx - NCOARSE;
        int m = j / 64, r = j % 64;
        float n = (float)r;
        float s, co;
        sincosf(g_w[m] * n, &s, &co);
        g_Ef[j] = expf(-g_d[m] * n);
        g_Sf[j] = s;
        g_Cf[j] = co;
    }
}

// ---------------- K3: fill Ps/Pc via angle addition ----------------
__global__ void k_fill()
{
    int t = blockIdx.x * blockDim.x + threadIdx.x;   // 0..T-1
    int m = blockIdx.y;
    int n = t + 1;
    int c = n >> 6, r = n & 63;
    float Ec = g_Ec[m * NC + c], Sc = g_Sc[m * NC + c], Cc = g_Cc[m * NC + c];
    float Ef = g_Ef[m * 64 + r], Sf = g_Sf[m * 64 + r], Cf = g_Cf[m * 64 + r];
    float E  = Ec * Ef;
    float sv = Sc * Cf + Cc * Sf;
    float cv = Cc * Cf - Sc * Sf;
    g_Ps[m * T + t] = E * sv;
    g_Pc[m * T + t] = E * cv;
}

// ---------------- K4: modal projections A,B per (a,m) ----------------
__global__ void k_AB(const float* __restrict__ forces)
{
    int gw   = (blockIdx.x * blockDim.x + threadIdx.x) >> 5;
    int lane = threadIdx.x & 31;
    if (gw >= AUD * MODES) return;
    int a = gw >> 6, m = gw & 63;
    const float* f  = forces + a * F;
    const float* ps = g_Ps + m * T;
    const float* pc = g_Pc + m * T;
    float A = 0.f, B = 0.f;
    for (int k = lane; k < F; k += 32) {
        float fk = f[k];
        A = fmaf(fk, pc[k], A);
        B = fmaf(fk, ps[k], B);
    }
    #pragma unroll
    for (int o = 16; o; o >>= 1) {
        A += __shfl_xor_sync(0xffffffffu, A, o);
        B += __shfl_xor_sync(0xffffffffu, B, o);
    }
    if (lane == 0) {
        float am = g_amp[a * MODES + m];
        g_cAB[m * AUD + a] = make_float2(am * A, am * B);
    }
}

// ---------------- K5: padded early signal  spad = [zeros | sum_m amp*Ps] ----------------
__global__ void k_sig()
{
    int idx = blockIdx.x * blockDim.x + threadIdx.x;  // AUD*8192
    int a = idx >> 13;
    int i = idx & 8191;
    float v = 0.f;
    if (i >= 4095) {
        int j = i - 4095;                              // 0..4096 (Ps has T cols, safe)
        const float* ap = g_amp + a * MODES;
        #pragma unroll 8
        for (int m = 0; m < MODES; m++)
            v = fmaf(ap[m], g_Ps[m * T + j], v);
    }
    g_spad[idx] = v;
}

// ---------------- K6: phase-1 conv, t in [0, 4096) ----------------
#define P1_TILE 512
#define P1_THR  128
__global__ void k_conv1(const float* __restrict__ forces, float* __restrict__ out)
{
    __shared__ float sh_f[F];
    __shared__ float sh_s[P1_TILE + F];    // 4608
    int a  = blockIdx.y;
    int t0 = blockIdx.x * P1_TILE;
    const float* f  = forces + a * F;
    const float* sp = g_spad + a * 8192 + t0;

    for (int i = threadIdx.x; i < F / 4; i += P1_THR)
        ((float4*)sh_f)[i] = ((const float4*)f)[i];
    for (int i = threadIdx.x; i < (P1_TILE + F) / 4; i += P1_THR)
        ((float4*)sh_s)[i] = ((const float4*)sp)[i];
    __syncthreads();

    int base = threadIdx.x * 4;
    float a0 = 0.f, a1 = 0.f, a2 = 0.f, a3 = 0.f;
    int klo = 4095 - (t0 + P1_TILE - 1);
    if (klo < 0) klo = 0;
    klo &= ~3;

    float4 sc = *(const float4*)(sh_s + base + klo);
    for (int k = klo; k < F; k += 4) {
        float4 f4 = *(const float4*)(sh_f + k);
        float4 sn = *(const float4*)(sh_s + base + k + 4);
        a0 = fmaf(f4.x, sc.x, a0); a1 = fmaf(f4.x, sc.y, a1); a2 = fmaf(f4.x, sc.z, a2); a3 = fmaf(f4.x, sc.w, a3);
        a0 = fmaf(f4.y, sc.y, a0); a1 = fmaf(f4.y, sc.z, a1); a2 = fmaf(f4.y, sc.w, a2); a3 = fmaf(f4.y, sn.x, a3);
        a0 = fmaf(f4.z, sc.z, a0); a1 = fmaf(f4.z, sc.w, a1); a2 = fmaf(f4.z, sn.x, a2); a3 = fmaf(f4.z, sn.y, a3);
        a0 = fmaf(f4.w, sc.w, a0); a1 = fmaf(f4.w, sn.x, a1); a2 = fmaf(f4.w, sn.y, a2); a3 = fmaf(f4.w, sn.z, a3);
        sc = sn;
    }
    float* o = out + a * T + t0 + base;
    o[0] = a0; o[1] = a1; o[2] = a2; o[3] = a3;
}

// ---------------- K7: phase-2 "GEMM", t in [4096, 32768) ----------------
__global__ void k_conv2(float* __restrict__ out)
{
    __shared__ float2 sh_c[MODES * AUD];
    for (int i = threadIdx.x; i < MODES * AUD; i += blockDim.x)
        sh_c[i] = g_cAB[i];
    __syncthreads();

    int j = blockIdx.x * blockDim.x + threadIdx.x;   // 0..28671
    if (j >= T - F) return;

    float acc[AUD];
    #pragma unroll
    for (int a = 0; a < AUD; a++) acc[a] = 0.f;

    #pragma unroll 4
    for (int m = 0; m < MODES; m++) {
        float ps = g_Ps[m * T + j];
        float pc = g_Pc[m * T + j];
        const float2* c = sh_c + m * AUD;
        #pragma unroll
        for (int a = 0; a < AUD; a++) {
            float2 cc = c[a];
            acc[a] = fmaf(cc.x, ps, fmaf(cc.y, pc, acc[a]));
        }
    }
    #pragma unroll
    for (int a = 0; a < AUD; a++)
        out[a * T + F + j] = acc[a];
}

// ---------------- launch ----------------
extern "C" void kernel_launch(void* const* d_in, const int* in_sizes, int n_in,
                              void* d_out, int out_size)
{
    const float* freq   = (const float*)d_in[0];
    const float* ampv   = (const float*)d_in[1];
    const float* ap     = (const float*)d_in[2];
    const float* bp     = (const float*)d_in[3];
    const float* forces = (const float*)d_in[4];
    float* out = (float*)d_out;

    k_setup<<<1, 64>>>(freq, ampv, ap, bp);

    int ncf = MODES * NC + MODES * 64;
    k_tables_cf<<<(ncf + 255) / 256, 256>>>();

    dim3 gf(T / 256, MODES);
    k_fill<<<gf, 256>>>();

    k_AB<<<(AUD * MODES * 32) / 256, 256>>>(forces);
    k_sig<<<(AUD * 8192) / 256, 256>>>();

    dim3 g1(F / P1_TILE, AUD);
    k_conv1<<<g1, P1_THR>>>(forces, out);

    k_conv2<<<(T - F) / 256, 256>>>(out);
}

// round 2
// speedup vs baseline: 1.5977x; 1.5977x over previous
#include <cuda_runtime.h>

#define MODES 64
#define AUD   16
#define T     32768
#define F     4096
#define NC    513

// ---------------- device scratch ----------------
__device__ float  g_d[MODES];
__device__ float  g_w[MODES];
__device__ float  g_amp[AUD * MODES];
__device__ float  g_Ec[MODES * NC], g_Sc[MODES * NC], g_Cc[MODES * NC];
__device__ float  g_Ef[MODES * 64], g_Sf[MODES * 64], g_Cf[MODES * 64];
__device__ float  g_Ps[MODES * T];
__device__ float  g_Pc[MODES * T];
__device__ float  g_spad[AUD * 8192];
__device__ float2 g_cAB[MODES * AUD];
__device__ float2 g_ABp[MODES * AUD * 8];        // per-(m,a) chunk partials
__device__ float  g_p1[36 * AUD * 512];          // conv1 partials

// active (tile, kchunk) pairs for the triangular phase-1 conv
__constant__ int c_ti[36] = {0, 1,1, 2,2,2, 3,3,3,3, 4,4,4,4,4,
                             5,5,5,5,5,5, 6,6,6,6,6,6,6, 7,7,7,7,7,7,7,7};
__constant__ int c_kc[36] = {7, 6,7, 5,6,7, 4,5,6,7, 3,4,5,6,7,
                             2,3,4,5,6,7, 1,2,3,4,5,6,7, 0,1,2,3,4,5,6,7};

// ---------------- K1: params + trig/exp tables (merged, 1 block per mode) ----------------
__global__ void k_tables(const float* __restrict__ freq_linear,
                         const float* __restrict__ amp_value,
                         const float* __restrict__ alpha_params,
                         const float* __restrict__ beta_params)
{
    int m = blockIdx.x;
    int tid = threadIdx.x;          // 128
    __shared__ float s_a[64], s_aw[64], s_b[64], s_bw[64];
    __shared__ float s_d, s_w;

    const float la0 = logf(0.6f), la1 = logf(60.0f);
    const float lb0 = logf(2e-8f), lb1 = logf(2e-6f);

    if (tid < 64) {
        float frac = (float)tid / 63.0f;
        float va = expf(la0 + (la1 - la0) * frac);
        float vb = expf(lb0 + (lb1 - lb0) * frac);
        float spa = log1pf(expf(alpha_params[m * 64 + tid]));
        float spb = log1pf(expf(beta_params [m * 64 + tid]));
        s_a[tid] = spa * va; s_aw[tid] = spa;
        s_b[tid] = spb * vb; s_bw[tid] = spb;
    } else if (tid < 80) {
        int a = tid - 64;
        float x = amp_value[a * MODES + m];
        float s = 1.0f / (1.0f + expf(-x));
        g_amp[a * MODES + m] = 2.0f * expf(2.30258509299404568f * logf(s)) + 1e-7f;
    }
    __syncthreads();
    if (tid == 0) {
        float asum = 0.f, awsum = 0.f, bsum = 0.f, bwsum = 0.f;
        for (int b = 0; b < 64; b++) {
            asum += s_a[b]; awsum += s_aw[b];
            bsum += s_b[b]; bwsum += s_bw[b];
        }
        float alpha = asum / awsum, beta = bsum / bwsum;
        float f2pi = freq_linear[m] * 6.28318530717958647692f;
        float lbd  = f2pi * f2pi;
        float dr   = 0.5f * (alpha + beta * lbd);
        s_d = dr / 16000.0f;
        s_w = sqrtf(lbd - dr * dr) / 16000.0f;
        g_d[m] = s_d; g_w[m] = s_w;
    }
    __syncthreads();
    float d = s_d, w = s_w;
    for (int i = tid; i < NC; i += 128) {
        float n = (float)(i << 6);
        float s, c;
        sincosf(w * n, &s, &c);
        g_Ec[m * NC + i] = expf(-d * n);
        g_Sc[m * NC + i] = s;
        g_Cc[m * NC + i] = c;
    }
    if (tid < 64) {
        float n = (float)tid;
        float s, c;
        sincosf(w * n, &s, &c);
        g_Ef[m * 64 + tid] = expf(-d * n);
        g_Sf[m * 64 + tid] = s;
        g_Cf[m * 64 + tid] = c;
    }
}

// ---------------- K2: Ps/Pc via angle addition ----------------
__global__ void k_fill()
{
    int t = blockIdx.x * blockDim.x + threadIdx.x;
    int m = blockIdx.y;
    int n = t + 1;
    int c = n >> 6, r = n & 63;
    float Ec = g_Ec[m * NC + c], Sc = g_Sc[m * NC + c], Cc = g_Cc[m * NC + c];
    float Ef = g_Ef[m * 64 + r], Sf = g_Sf[m * 64 + r], Cf = g_Cf[m * 64 + r];
    float E  = Ec * Ef;
    g_Ps[m * T + t] = E * (Sc * Cf + Cc * Sf);
    g_Pc[m * T + t] = E * (Cc * Cf - Sc * Sf);
}

// ---------------- K3: chunked modal projections ----------------
__global__ void k_ABp(const float* __restrict__ forces)
{
    __shared__ float sps[512], spc[512];
    int m = blockIdx.x, kc = blockIdx.y;
    int k0 = kc << 9;
    int tid = threadIdx.x;              // 256
    sps[tid]       = g_Ps[m * T + k0 + tid];
    sps[tid + 256] = g_Ps[m * T + k0 + tid + 256];
    spc[tid]       = g_Pc[m * T + k0 + tid];
    spc[tid + 256] = g_Pc[m * T + k0 + tid + 256];
    __syncthreads();

    int wrp = tid >> 5, lane = tid & 31;
    int a0 = wrp * 2, a1 = a0 + 1;
    const float* f0 = forces + a0 * F + k0;
    const float* f1 = forces + a1 * F + k0;
    float A0 = 0.f, B0 = 0.f, A1 = 0.f, B1 = 0.f;
    #pragma unroll
    for (int k = lane; k < 512; k += 32) {
        float pc = spc[k], ps = sps[k];
        float x0 = f0[k], x1 = f1[k];
        A0 = fmaf(x0, pc, A0); B0 = fmaf(x0, ps, B0);
        A1 = fmaf(x1, pc, A1); B1 = fmaf(x1, ps, B1);
    }
    #pragma unroll
    for (int o = 16; o; o >>= 1) {
        A0 += __shfl_xor_sync(0xffffffffu, A0, o);
        B0 += __shfl_xor_sync(0xffffffffu, B0, o);
        A1 += __shfl_xor_sync(0xffffffffu, A1, o);
        B1 += __shfl_xor_sync(0xffffffffu, B1, o);
    }
    if (lane == 0) {
        g_ABp[(m * AUD + a0) * 8 + kc] = make_float2(A0, B0);
        g_ABp[(m * AUD + a1) * 8 + kc] = make_float2(A1, B1);
    }
}

// ---------------- K4: reduce projections, apply amp ----------------
__global__ void k_ABr()
{
    int i = blockIdx.x * blockDim.x + threadIdx.x;   // 1024
    int m = i >> 4, a = i & 15;
    float A = 0.f, B = 0.f;
    #pragma unroll
    for (int kc = 0; kc < 8; kc++) {
        float2 p = g_ABp[i * 8 + kc];
        A += p.x; B += p.y;
    }
    float am = g_amp[a * MODES + m];
    g_cAB[m * AUD + a] = make_float2(am * A, am * B);
}

// ---------------- K5: padded early signal ----------------
__global__ void k_sig()
{
    int idx = blockIdx.x * blockDim.x + threadIdx.x;
    int a = idx >> 13;
    int i = idx & 8191;
    float v = 0.f;
    if (i >= 4095) {
        int j = i - 4095;
        const float* ap = g_amp + a * MODES;
        #pragma unroll 8
        for (int m = 0; m < MODES; m++)
            v = fmaf(ap[m], g_Ps[m * T + j], v);
    }
    g_spad[idx] = v;
}

// ---------------- K6: balanced phase-1 conv partials ----------------
__global__ void __launch_bounds__(128) k_conv1p(const float* __restrict__ forces)
{
    __shared__ float sh_f[512];
    __shared__ float sh_s[1024];
    int p = blockIdx.x, a = blockIdx.y;
    int ti = c_ti[p], kc = c_kc[p];
    int t0 = ti << 9, k0 = kc << 9;
    int tid = threadIdx.x;

    ((float4*)sh_f)[tid]       = ((const float4*)(forces + a * F + k0))[tid];
    ((float4*)sh_s)[tid]       = ((const float4*)(g_spad + a * 8192 + t0 + k0))[tid];
    ((float4*)sh_s)[tid + 128] = ((const float4*)(g_spad + a * 8192 + t0 + k0))[tid + 128];
    __syncthreads();

    int base = tid * 4;
    float a0 = 0.f, a1 = 0.f, a2 = 0.f, a3 = 0.f;
    float4 sc = *(const float4*)(sh_s + base);
    #pragma unroll 4
    for (int k = 0; k < 512; k += 4) {
        float4 f4 = *(const float4*)(sh_f + k);
        float4 sn = *(const float4*)(sh_s + base + k + 4);
        a0 = fmaf(f4.x, sc.x, a0); a1 = fmaf(f4.x, sc.y, a1); a2 = fmaf(f4.x, sc.z, a2); a3 = fmaf(f4.x, sc.w, a3);
        a0 = fmaf(f4.y, sc.y, a0); a1 = fmaf(f4.y, sc.z, a1); a2 = fmaf(f4.y, sc.w, a2); a3 = fmaf(f4.y, sn.x, a3);
        a0 = fmaf(f4.z, sc.z, a0); a1 = fmaf(f4.z, sc.w, a1); a2 = fmaf(f4.z, sn.x, a2); a3 = fmaf(f4.z, sn.y, a3);
        a0 = fmaf(f4.w, sc.w, a0); a1 = fmaf(f4.w, sn.x, a1); a2 = fmaf(f4.w, sn.y, a2); a3 = fmaf(f4.w, sn.z, a3);
        sc = sn;
    }
    *(float4*)(g_p1 + (p * AUD + a) * 512 + base) = make_float4(a0, a1, a2, a3);
}

// ---------------- K7: phase-1 reduce ----------------
__global__ void k_conv1r(float* __restrict__ out)
{
    int ti = blockIdx.x, a = blockIdx.y, j = threadIdx.x;   // 512 threads
    int s = (ti * (ti + 1)) >> 1;
    float v = 0.f;
    for (int c = 0; c <= ti; c++)
        v += g_p1[((s + c) * AUD + a) * 512 + j];
    out[a * T + (ti << 9) + j] = v;
}

// ---------------- K8: phase-2 GEMM ----------------
__global__ void __launch_bounds__(128) k_conv2(float* __restrict__ out)
{
    __shared__ float2 sh_c[MODES * AUD];
    for (int i = threadIdx.x; i < MODES * AUD; i += 128)
        sh_c[i] = g_cAB[i];
    __syncthreads();

    int j = blockIdx.x * 128 + threadIdx.x;   // 0..28671

    float acc[AUD];
    #pragma unroll
    for (int a = 0; a < AUD; a++) acc[a] = 0.f;

    #pragma unroll 4
    for (int m = 0; m < MODES; m++) {
        float ps = g_Ps[m * T + j];
        float pc = g_Pc[m * T + j];
        const float2* c = sh_c + m * AUD;
        #pragma unroll
        for (int a = 0; a < AUD; a++) {
            float2 cc = c[a];
            acc[a] = fmaf(cc.x, ps, fmaf(cc.y, pc, acc[a]));
        }
    }
    #pragma unroll
    for (int a = 0; a < AUD; a++)
        out[a * T + F + j] = acc[a];
}

// ---------------- launch ----------------
extern "C" void kernel_launch(void* const* d_in, const int* in_sizes, int n_in,
                              void* d_out, int out_size)
{
    const float* freq   = (const float*)d_in[0];
    const float* ampv   = (const float*)d_in[1];
    const float* ap     = (const float*)d_in[2];
    const float* bp     = (const float*)d_in[3];
    const float* forces = (const float*)d_in[4];
    float* out = (float*)d_out;

    k_tables<<<MODES, 128>>>(freq, ampv, ap, bp);
    k_fill<<<dim3(T / 256, MODES), 256>>>();
    k_ABp<<<dim3(MODES, 8), 256>>>(forces);
    k_sig<<<(AUD * 8192) / 256, 256>>>();
    k_ABr<<<4, 256>>>();
    k_conv1p<<<dim3(36, AUD), 128>>>(forces);
    k_conv2<<<224, 128>>>(out);
    k_conv1r<<<dim3(8, AUD), 512>>>(out);
}

// round 3
// speedup vs baseline: 1.6596x; 1.0387x over previous
#include <cuda_runtime.h>

#define MODES 64
#define AUD   16
#define T     32768
#define F     4096
#define NC    513

// ---------------- device scratch ----------------
__device__ float  g_d[MODES];
__device__ float  g_w[MODES];
__device__ float  g_amp[AUD * MODES];
__device__ float  g_Ec[MODES * NC], g_Sc[MODES * NC], g_Cc[MODES * NC];
__device__ float  g_Ef[MODES * 64], g_Sf[MODES * 64], g_Cf[MODES * 64];
__device__ float  g_Ps[MODES * T];
__device__ float  g_Pc[MODES * T];
__device__ float  g_spad[AUD * 8192];
__device__ float2 g_cAB[MODES * AUD];
__device__ float  g_p1[36 * AUD * 512];

// active (tile, kchunk) pairs for the triangular phase-1 conv
__constant__ int c_ti[36] = {0, 1,1, 2,2,2, 3,3,3,3, 4,4,4,4,4,
                             5,5,5,5,5,5, 6,6,6,6,6,6,6, 7,7,7,7,7,7,7,7};
__constant__ int c_kc[36] = {7, 6,7, 5,6,7, 4,5,6,7, 3,4,5,6,7,
                             2,3,4,5,6,7, 1,2,3,4,5,6,7, 0,1,2,3,4,5,6,7};

// ---------------- K1: params + trig/exp tables ----------------
__global__ void k_tables(const float* __restrict__ freq_linear,
                         const float* __restrict__ amp_value,
                         const float* __restrict__ alpha_params,
                         const float* __restrict__ beta_params)
{
    int m = blockIdx.x;
    int tid = threadIdx.x;          // 128
    __shared__ float s_a[64], s_aw[64], s_b[64], s_bw[64];
    __shared__ float s_d, s_w;

    const float la0 = logf(0.6f), la1 = logf(60.0f);
    const float lb0 = logf(2e-8f), lb1 = logf(2e-6f);

    if (tid < 64) {
        float frac = (float)tid / 63.0f;
        float va = expf(la0 + (la1 - la0) * frac);
        float vb = expf(lb0 + (lb1 - lb0) * frac);
        float spa = log1pf(expf(alpha_params[m * 64 + tid]));
        float spb = log1pf(expf(beta_params [m * 64 + tid]));
        s_a[tid] = spa * va; s_aw[tid] = spa;
        s_b[tid] = spb * vb; s_bw[tid] = spb;
    } else if (tid < 80) {
        int a = tid - 64;
        float x = amp_value[a * MODES + m];
        float s = 1.0f / (1.0f + expf(-x));
        g_amp[a * MODES + m] = 2.0f * expf(2.30258509299404568f * logf(s)) + 1e-7f;
    }
    __syncthreads();
    if (tid == 0) {
        float asum = 0.f, awsum = 0.f, bsum = 0.f, bwsum = 0.f;
        for (int b = 0; b < 64; b++) {
            asum += s_a[b]; awsum += s_aw[b];
            bsum += s_b[b]; bwsum += s_bw[b];
        }
        float alpha = asum / awsum, beta = bsum / bwsum;
        float f2pi = freq_linear[m] * 6.28318530717958647692f;
        float lbd  = f2pi * f2pi;
        float dr   = 0.5f * (alpha + beta * lbd);
        s_d = dr / 16000.0f;
        s_w = sqrtf(lbd - dr * dr) / 16000.0f;
        g_d[m] = s_d; g_w[m] = s_w;
    }
    __syncthreads();
    float d = s_d, w = s_w;
    for (int i = tid; i < NC; i += 128) {
        float n = (float)(i << 6);
        float s, c;
        sincosf(w * n, &s, &c);
        g_Ec[m * NC + i] = expf(-d * n);
        g_Sc[m * NC + i] = s;
        g_Cc[m * NC + i] = c;
    }
    if (tid < 64) {
        float n = (float)tid;
        float s, c;
        sincosf(w * n, &s, &c);
        g_Ef[m * 64 + tid] = expf(-d * n);
        g_Sf[m * 64 + tid] = s;
        g_Cf[m * 64 + tid] = c;
    }
}

// ---------------- K2: Ps/Pc via angle addition ----------------
__global__ void k_fill()
{
    int t = blockIdx.x * blockDim.x + threadIdx.x;
    int m = blockIdx.y;
    int n = t + 1;
    int c = n >> 6, r = n & 63;
    float Ec = g_Ec[m * NC + c], Sc = g_Sc[m * NC + c], Cc = g_Cc[m * NC + c];
    float Ef = g_Ef[m * 64 + r], Sf = g_Sf[m * 64 + r], Cf = g_Cf[m * 64 + r];
    float E  = Ec * Ef;
    g_Ps[m * T + t] = E * (Sc * Cf + Cc * Sf);
    g_Pc[m * T + t] = E * (Cc * Cf - Sc * Sf);
}

// ---------------- K3 merged: [sig blocks 0..31] + [AB blocks 32..95] ----------------
__global__ void __launch_bounds__(256) k_mid(const float* __restrict__ forces)
{
    __shared__ float sbuf[1024 + 32];
    int tid = threadIdx.x;

    if (blockIdx.x < 32) {
        // ---- signal for early region: spad[a][i], i = 4095 + j holds signal[j] ----
        // load amps into smem
        for (int i = tid; i < AUD * MODES; i += 256) sbuf[i] = g_amp[i];
        __syncthreads();
        int i = blockIdx.x * 256 + tid;                 // 0..8191
        float acc[AUD];
        #pragma unroll
        for (int a = 0; a < AUD; a++) acc[a] = 0.f;
        if (i >= 4095) {
            int j = i - 4095;                           // 0..4096
            #pragma unroll 4
            for (int m = 0; m < MODES; m++) {
                float ps = g_Ps[m * T + j];
                #pragma unroll
                for (int a = 0; a < AUD; a++)
                    acc[a] = fmaf(sbuf[a * MODES + m], ps, acc[a]);
            }
        }
        #pragma unroll
        for (int a = 0; a < AUD; a++)
            g_spad[a * 8192 + i] = acc[a];
    } else {
        // ---- modal projections: one block per mode, loop k-chunks ----
        int m = blockIdx.x - 32;
        float* sps = sbuf;                 // 512
        float* spc = sbuf + 512;           // 512
        int wrp = tid >> 5, lane = tid & 31;
        int a0 = wrp * 2, a1 = a0 + 1;
        float A0 = 0.f, B0 = 0.f, A1 = 0.f, B1 = 0.f;
        for (int kc = 0; kc < 8; kc++) {
            int k0 = kc << 9;
            __syncthreads();
            sps[tid]       = g_Ps[m * T + k0 + tid];
            sps[tid + 256] = g_Ps[m * T + k0 + tid + 256];
            spc[tid]       = g_Pc[m * T + k0 + tid];
            spc[tid + 256] = g_Pc[m * T + k0 + tid + 256];
            __syncthreads();
            const float* f0 = forces + a0 * F + k0;
            const float* f1 = forces + a1 * F + k0;
            #pragma unroll 4
            for (int k = lane; k < 512; k += 32) {
                float pc = spc[k], ps = sps[k];
                float x0 = f0[k], x1 = f1[k];
                A0 = fmaf(x0, pc, A0); B0 = fmaf(x0, ps, B0);
                A1 = fmaf(x1, pc, A1); B1 = fmaf(x1, ps, B1);
            }
        }
        #pragma unroll
        for (int o = 16; o; o >>= 1) {
            A0 += __shfl_xor_sync(0xffffffffu, A0, o);
            B0 += __shfl_xor_sync(0xffffffffu, B0, o);
            A1 += __shfl_xor_sync(0xffffffffu, A1, o);
            B1 += __shfl_xor_sync(0xffffffffu, B1, o);
        }
        if (lane == 0) {
            float am0 = g_amp[a0 * MODES + m];
            float am1 = g_amp[a1 * MODES + m];
            g_cAB[m * AUD + a0] = make_float2(am0 * A0, am0 * B0);
            g_cAB[m * AUD + a1] = make_float2(am1 * A1, am1 * B1);
        }
    }
}

// ---------------- K4 merged: [conv1 partials 0..575] + [conv2 576..799] ----------------
__global__ void __launch_bounds__(128) k_conv(const float* __restrict__ forces,
                                              float* __restrict__ out)
{
    __shared__ float smem_buf[2048];       // 8KB, aliased per branch
    int tid = threadIdx.x;

    if (blockIdx.x < 576) {
        // ---- balanced phase-1 conv partials ----
        int b = blockIdx.x;
        int p = b % 36, a = b / 36;
        int ti = c_ti[p], kc = c_kc[p];
        int t0 = ti << 9, k0 = kc << 9;
        float* sh_f = smem_buf;            // 512
        float* sh_s = smem_buf + 512;      // 1024

        ((float4*)sh_f)[tid]       = ((const float4*)(forces + a * F + k0))[tid];
        ((float4*)sh_s)[tid]       = ((const float4*)(g_spad + a * 8192 + t0 + k0))[tid];
        ((float4*)sh_s)[tid + 128] = ((const float4*)(g_spad + a * 8192 + t0 + k0))[tid + 128];
        __syncthreads();

        int base = tid * 4;
        float a0 = 0.f, a1 = 0.f, a2 = 0.f, a3 = 0.f;
        float4 sc = *(const float4*)(sh_s + base);
        #pragma unroll 4
        for (int k = 0; k < 512; k += 4) {
            float4 f4 = *(const float4*)(sh_f + k);
            float4 sn = *(const float4*)(sh_s + base + k + 4);
            a0 = fmaf(f4.x, sc.x, a0); a1 = fmaf(f4.x, sc.y, a1); a2 = fmaf(f4.x, sc.z, a2); a3 = fmaf(f4.x, sc.w, a3);
            a0 = fmaf(f4.y, sc.y, a0); a1 = fmaf(f4.y, sc.z, a1); a2 = fmaf(f4.y, sc.w, a2); a3 = fmaf(f4.y, sn.x, a3);
            a0 = fmaf(f4.z, sc.z, a0); a1 = fmaf(f4.z, sc.w, a1); a2 = fmaf(f4.z, sn.x, a2); a3 = fmaf(f4.z, sn.y, a3);
            a0 = fmaf(f4.w, sc.w, a0); a1 = fmaf(f4.w, sn.x, a1); a2 = fmaf(f4.w, sn.y, a2); a3 = fmaf(f4.w, sn.z, a3);
            sc = sn;
        }
        *(float4*)(g_p1 + (p * AUD + a) * 512 + base) = make_float4(a0, a1, a2, a3);
    } else {
        // ---- phase-2 GEMM ----
        float2* sh_c = (float2*)smem_buf;  // 1024 float2 = 8KB
        for (int i = tid; i < MODES * AUD; i += 128)
            sh_c[i] = g_cAB[i];
        __syncthreads();

        int j = (blockIdx.x - 576) * 128 + tid;   // 0..28671
        float acc[AUD];
        #pragma unroll
        for (int a = 0; a < AUD; a++) acc[a] = 0.f;

        #pragma unroll 4
        for (int m = 0; m < MODES; m++) {
            float ps = g_Ps[m * T + j];
            float pc = g_Pc[m * T + j];
            const float2* c = sh_c + m * AUD;
            #pragma unroll
            for (int a = 0; a < AUD; a++) {
                float2 cc = c[a];
                acc[a] = fmaf(cc.x, ps, fmaf(cc.y, pc, acc[a]));
            }
        }
        #pragma unroll
        for (int a = 0; a < AUD; a++)
            out[a * T + F + j] = acc[a];
    }
}

// ---------------- K5: phase-1 reduce ----------------
__global__ void k_conv1r(float* __restrict__ out)
{
    int ti = blockIdx.x, a = blockIdx.y, j = threadIdx.x;   // 512 threads
    int s = (ti * (ti + 1)) >> 1;
    float v = 0.f;
    for (int c = 0; c <= ti; c++)
        v += g_p1[((s + c) * AUD + a) * 512 + j];
    out[a * T + (ti << 9) + j] = v;
}

// ---------------- launch ----------------
extern "C" void kernel_launch(void* const* d_in, const int* in_sizes, int n_in,
                              void* d_out, int out_size)
{
    const float* freq   = (const float*)d_in[0];
    const float* ampv   = (const float*)d_in[1];
    const float* ap     = (const float*)d_in[2];
    const float* bp     = (const float*)d_in[3];
    const float* forces = (const float*)d_in[4];
    float* out = (float*)d_out;

    k_tables<<<MODES, 128>>>(freq, ampv, ap, bp);
    k_fill<<<dim3(T / 256, MODES), 256>>>();
    k_mid<<<96, 256>>>(forces);
    k_conv<<<800, 128>>>(forces, out);
    k_conv1r<<<dim3(8, AUD), 512>>>(out);
}